// round 15
// baseline (speedup 1.0000x reference)
#include <cuda_runtime.h>

// SEIR scan, two-pass chunked recomputation.
// Output layout: [4, T, B] — planes S, E, I, R.
//
// Pass 1 (~25us): 64 blocks x 128 threads; X staged through dynamic smem with
//         a double-buffered cp.async pipeline (TK=128 rows, wait_group 1),
//         8-deep LDS ring, 10-FP-op step (20-cyc chain == 20-cyc issue floor),
//         float4 boundary stores every STEP steps.
// Pass 2 (~52us): 1024-block (chunk, channel/4) grid, one 16-step chunk per
//         block; plain (L2-cached) X loads, float4 evict-first output stores.

#define STEP   16
#define TK     128         // rows per smem tile
#define NBUF   2
#define MAXB   8192
#define MAXC   256         // supports T up to 4096

__device__ float4 g_bnd[MAXC * MAXB];   // interleaved (S,E,I,R) boundaries

// ---- cp.async helpers ----
__device__ __forceinline__ void cp_async16(void* smem_dst, const void* gsrc)
{
    unsigned s = (unsigned)__cvta_generic_to_shared(smem_dst);
    asm volatile("cp.async.cg.shared.global [%0], [%1], 16;"
                 :: "r"(s), "l"(gsrc));
}
#define CP_COMMIT() asm volatile("cp.async.commit_group;" ::: "memory")
#define CP_WAIT1()  asm volatile("cp.async.wait_group 1;"  ::: "memory")

// 10-op SEIR step; invN folded into wbN.
//   a = (wbN*I)*S ; b = ws*E ; c = wg*I
//   S' = S - x*a ; E' = E + x*(a-b) ; I' = I + x*(b-c) ; R' = R + x*c
__device__ __forceinline__ void seir_step10(float x, float wbN, float wg, float ws,
                                            float& S, float& E, float& I, float& R)
{
    const float a  = (wbN * I) * S;
    const float b  = ws * E;
    const float c  = wg * I;
    const float ab = a - b;
    const float bc = b - c;
    S = fmaf(-x, a, S);
    E = fmaf(x, ab, E);
    I = fmaf(x, bc, I);
    R = fmaf(x, c, R);
}

// ---------------------------------------------------------------- pass 1
template<int B_>
__global__ __launch_bounds__(128, 1)
void seir_pass1(const float* __restrict__ X,
                const float* __restrict__ w_beta,
                const float* __restrict__ w_gamma,
                const float* __restrict__ w_sigma,
                const float* __restrict__ S0,
                const float* __restrict__ I0,
                const float* __restrict__ R0,
                const float* __restrict__ Nvec,
                int NS, int T)
{
    extern __shared__ __align__(16) float tile[];   // [NBUF][TK][128]

    const int tid  = threadIdx.x;
    const int w    = tid >> 5;
    const int lane = tid & 31;
    const int b    = blockIdx.x * 128 + tid;
    const int col0 = blockIdx.x * 128;

    const float invN = 1.0f / Nvec[b];
    const float wbN  = w_beta[b] * invN;
    const float wg   = w_gamma[b];
    const float ws   = w_sigma[b];

    float S = S0[b];
    float E = 0.0f;
    float I = I0[b];
    float R = R0[b];

    g_bnd[b] = make_float4(S, E, I, R);     // boundary 0
    if (NS <= 0) return;

    const float* __restrict__ xcol = X + col0 + (size_t)lane * 4;
    const int Tm1 = T - 1;

    // one tile = TK rows x 128 channels; each warp loads TK/4 rows
    auto issue_tile = [&](int ti, int bufsel) {
        float* bufp = tile + (size_t)bufsel * TK * 128;
#pragma unroll
        for (int k = 0; k < TK / 4; ++k) {
            const int kr   = k * 4 + w;
            const int trow = min(ti * TK + kr, Tm1);   // clamp: always valid
            cp_async16(bufp + kr * 128 + lane * 4,
                       xcol + (size_t)trow * B_);
        }
    };

    const int nfull = NS / TK;
    const int rem   = NS - nfull * TK;

    issue_tile(0, 0); CP_COMMIT();
    issue_tile(1, 1); CP_COMMIT();

    for (int i = 0; i < nfull; ++i) {
        CP_WAIT1();              // tile i complete (tile i+1 may be pending)
        __syncthreads();

        const int buf = i & 1;
        const float* __restrict__ bp = tile + (size_t)buf * TK * 128 + tid;
        const int t0 = i * TK;

        // 8-deep register ring over conflict-free LDS
        float xr[8];
#pragma unroll
        for (int j = 0; j < 8; ++j) xr[j] = bp[j * 128];

#pragma unroll
        for (int k = 0; k < TK; ++k) {
            const float x = xr[k & 7];
            if (k + 8 < TK) xr[k & 7] = bp[(k + 8) * 128];
            seir_step10(x, wbN, wg, ws, S, E, I, R);
            if (((k + 1) & (STEP - 1)) == 0) {        // static: every 16th
                const int c = (t0 + k + 1) / STEP;
                g_bnd[c * B_ + b] = make_float4(S, E, I, R);
            }
        }

        __syncthreads();         // everyone done reading buf
        issue_tile(i + 2, buf);  // refill same buffer for tile i+2 (clamped)
        CP_COMMIT();
    }

    if (rem > 0) {
        CP_WAIT1();              // tile nfull complete
        __syncthreads();
        const int buf = nfull & 1;
        const float* __restrict__ bp = tile + (size_t)buf * TK * 128 + tid;
        const int t0 = nfull * TK;
        for (int k = 0; k < rem; ++k) {
            const float x = bp[k * 128];
            seir_step10(x, wbN, wg, ws, S, E, I, R);
            if (((t0 + k + 1) & (STEP - 1)) == 0) {
                const int c = (t0 + k + 1) / STEP;
                g_bnd[c * B_ + b] = make_float4(S, E, I, R);
            }
        }
    }
}

// ---------------------------------------------------------------- pass 2
__global__ __launch_bounds__(256)
void seir_pass2(const float* __restrict__ X,
                const float* __restrict__ w_beta,
                const float* __restrict__ w_gamma,
                const float* __restrict__ w_sigma,
                const float* __restrict__ Nvec,
                float* __restrict__ out,
                int T, int B)
{
    const int j = blockIdx.x * blockDim.x + threadIdx.x;   // channel/4
    const int b = j * 4;
    if (b >= B) return;

    const int c  = blockIdx.y;
    const int t0 = c * STEP;
    if (t0 >= T) return;
    const int nst = min(STEP, T - t0) - 1;

    const float4 wb = *(const float4*)(w_beta  + b);
    const float4 wg = *(const float4*)(w_gamma + b);
    const float4 ws = *(const float4*)(w_sigma + b);
    const float4 nv = *(const float4*)(Nvec    + b);
    const float4 wbN = make_float4(wb.x / nv.x, wb.y / nv.y,
                                   wb.z / nv.z, wb.w / nv.w);

    // load 4 interleaved boundary float4s and transpose
    const int bi = c * B + b;
    const float4 b0 = g_bnd[bi + 0];
    const float4 b1 = g_bnd[bi + 1];
    const float4 b2 = g_bnd[bi + 2];
    const float4 b3 = g_bnd[bi + 3];
    float4 S = make_float4(b0.x, b1.x, b2.x, b3.x);
    float4 E = make_float4(b0.y, b1.y, b2.y, b3.y);
    float4 I = make_float4(b0.z, b1.z, b2.z, b3.z);
    float4 R = make_float4(b0.w, b1.w, b2.w, b3.w);

    const size_t TB = (size_t)T * (size_t)B;
    float* __restrict__ oS = out;
    float* __restrict__ oE = out + TB;
    float* __restrict__ oI = out + 2 * TB;
    float* __restrict__ oR = out + 3 * TB;

    size_t r = (size_t)t0 * B + b;
    __stcs((float4*)(oS + r), S);
    __stcs((float4*)(oE + r), E);
    __stcs((float4*)(oI + r), I);
    __stcs((float4*)(oR + r), R);

    const float* __restrict__ xp = X + (size_t)t0 * B + b;
    float4 xn = (nst > 0) ? *(const float4*)xp : make_float4(0.f, 0.f, 0.f, 0.f);

    if (nst == STEP - 1) {
#pragma unroll
        for (int i = 0; i < STEP - 1; ++i) {
            const float4 x = xn;
            if (i + 1 < STEP - 1)
                xn = *(const float4*)(xp + (i + 1) * B);
            seir_step10(x.x, wbN.x, wg.x, ws.x, S.x, E.x, I.x, R.x);
            seir_step10(x.y, wbN.y, wg.y, ws.y, S.y, E.y, I.y, R.y);
            seir_step10(x.z, wbN.z, wg.z, ws.z, S.z, E.z, I.z, R.z);
            seir_step10(x.w, wbN.w, wg.w, ws.w, S.w, E.w, I.w, R.w);
            r += B;
            __stcs((float4*)(oS + r), S);
            __stcs((float4*)(oE + r), E);
            __stcs((float4*)(oI + r), I);
            __stcs((float4*)(oR + r), R);
        }
    } else {
        for (int i = 0; i < nst; ++i) {
            const float4 x = xn;
            if (i + 1 < nst)
                xn = *(const float4*)(xp + (i + 1) * B);
            seir_step10(x.x, wbN.x, wg.x, ws.x, S.x, E.x, I.x, R.x);
            seir_step10(x.y, wbN.y, wg.y, ws.y, S.y, E.y, I.y, R.y);
            seir_step10(x.z, wbN.z, wg.z, ws.z, S.z, E.z, I.z, R.z);
            seir_step10(x.w, wbN.w, wg.w, ws.w, S.w, E.w, I.w, R.w);
            r += B;
            __stcs((float4*)(oS + r), S);
            __stcs((float4*)(oE + r), E);
            __stcs((float4*)(oI + r), I);
            __stcs((float4*)(oR + r), R);
        }
    }
}

// ------------------------------------------------ fallback (shape safety)
__global__ void seir_fallback(const float* __restrict__ X,
                              const float* __restrict__ w_beta,
                              const float* __restrict__ w_gamma,
                              const float* __restrict__ w_sigma,
                              const float* __restrict__ S0,
                              const float* __restrict__ I0,
                              const float* __restrict__ R0,
                              const float* __restrict__ Nvec,
                              float* __restrict__ out, int T, int B)
{
    const int b = blockIdx.x * blockDim.x + threadIdx.x;
    if (b >= B) return;
    const float invN = 1.0f / Nvec[b];
    const float wbN = w_beta[b] * invN;
    const float wg = w_gamma[b], ws = w_sigma[b];
    float S = S0[b], E = 0.0f, I = I0[b], R = R0[b];
    const size_t TB = (size_t)T * B;
    out[b] = S; out[TB + b] = E; out[2 * TB + b] = I; out[3 * TB + b] = R;
    for (int t = 0; t < T - 1; ++t) {
        const float x = X[(size_t)t * B + b];
        seir_step10(x, wbN, wg, ws, S, E, I, R);
        const size_t r = (size_t)(t + 1) * B + b;
        out[r] = S; out[TB + r] = E; out[2 * TB + r] = I; out[3 * TB + r] = R;
    }
}

extern "C" void kernel_launch(void* const* d_in, const int* in_sizes, int n_in,
                              void* d_out, int out_size)
{
    const float* X      = (const float*)d_in[0];
    const float* w_beta = (const float*)d_in[1];
    const float* w_gamma= (const float*)d_in[2];
    const float* w_sigma= (const float*)d_in[3];
    const float* S0     = (const float*)d_in[4];
    const float* I0     = (const float*)d_in[5];
    const float* R0     = (const float*)d_in[6];
    const float* Nvec   = (const float*)d_in[7];
    float* out = (float*)d_out;

    const int B = in_sizes[1];         // w_beta is [B]
    const int T = in_sizes[0] / B;     // X is [T, B]
    const int chunks = (T + STEP - 1) / STEP;

    if (B == 8192 && chunks <= MAXC && T >= 2) {
        const int NS = (chunks - 1) * STEP;
        const int smem = NBUF * TK * 128 * (int)sizeof(float);   // 128 KB
        cudaFuncSetAttribute(seir_pass1<8192>,
                             cudaFuncAttributeMaxDynamicSharedMemorySize, smem);
        seir_pass1<8192><<<8192 / 128, 128, smem>>>(X, w_beta, w_gamma,
                                                    w_sigma, S0, I0, R0,
                                                    Nvec, NS, T);
        dim3 g2(8192 / 4 / 256, chunks);
        seir_pass2<<<g2, 256>>>(X, w_beta, w_gamma, w_sigma, Nvec,
                                out, T, B);
    } else {
        seir_fallback<<<(B + 127) / 128, 128>>>(X, w_beta, w_gamma, w_sigma,
                                                S0, I0, R0, Nvec, out, T, B);
    }
}

// round 16
// speedup vs baseline: 1.4054x; 1.4054x over previous
#include <cuda_runtime.h>

// SEIR scan — single fused kernel.
// Output layout: [4, T, B] — planes S, E, I, R.
//
// 128 blocks x 64 threads; each thread owns ONE channel and scans all T
// steps serially, storing every state directly (STG.32, warp-coalesced
// 128B per plane per step). X is staged through a triple-buffered cp.async
// smem pipeline. Total traffic = X once (64MB) + output once (256MB);
// no boundary scratch, no recomputation, no second kernel.

#define TK     64          // rows per smem tile
#define NBUF   3
#define CPB    64          // channels per block

// ---- cp.async helpers ----
__device__ __forceinline__ void cp_async16(void* smem_dst, const void* gsrc)
{
    unsigned s = (unsigned)__cvta_generic_to_shared(smem_dst);
    asm volatile("cp.async.cg.shared.global [%0], [%1], 16;"
                 :: "r"(s), "l"(gsrc));
}
#define CP_COMMIT() asm volatile("cp.async.commit_group;" ::: "memory")
#define CP_WAIT2()  asm volatile("cp.async.wait_group 2;"  ::: "memory")

// 10-op SEIR step; invN folded into wbN.
//   a = (wbN*I)*S ; b = ws*E ; c = wg*I
//   S' = S - x*a ; E' = E + x*(a-b) ; I' = I + x*(b-c) ; R' = R + x*c
__device__ __forceinline__ void seir_step10(float x, float wbN, float wg, float ws,
                                            float& S, float& E, float& I, float& R)
{
    const float a  = (wbN * I) * S;
    const float b  = ws * E;
    const float c  = wg * I;
    const float ab = a - b;
    const float bc = b - c;
    S = fmaf(-x, a, S);
    E = fmaf(x, ab, E);
    I = fmaf(x, bc, I);
    R = fmaf(x, c, R);
}

// ---------------------------------------------------------------- fused
template<int B_>
__global__ __launch_bounds__(CPB, 1)
void seir_fused(const float* __restrict__ X,
                const float* __restrict__ w_beta,
                const float* __restrict__ w_gamma,
                const float* __restrict__ w_sigma,
                const float* __restrict__ S0,
                const float* __restrict__ I0,
                const float* __restrict__ R0,
                const float* __restrict__ Nvec,
                float* __restrict__ out,
                int T)
{
    extern __shared__ __align__(16) float tile[];   // [NBUF][TK][CPB]

    const int tid  = threadIdx.x;
    const int b    = blockIdx.x * CPB + tid;
    const int col0 = blockIdx.x * CPB;

    const float invN = 1.0f / Nvec[b];
    const float wbN  = w_beta[b] * invN;
    const float wg   = w_gamma[b];
    const float ws   = w_sigma[b];

    float S = S0[b];
    float E = 0.0f;
    float I = I0[b];
    float R = R0[b];

    const size_t TB = (size_t)T * (size_t)B_;
    float* __restrict__ oS = out;
    float* __restrict__ oE = out + TB;
    float* __restrict__ oI = out + 2 * TB;
    float* __restrict__ oR = out + 3 * TB;

    // row 0 = initial state
    size_t r = (size_t)b;
    __stcs(oS + r, S);
    __stcs(oE + r, E);
    __stcs(oI + r, I);
    __stcs(oR + r, R);

    const int NS = T - 1;
    if (NS <= 0) return;

    const int Tm1 = T - 1;

    // tile loader: TK rows x CPB channels; 64 threads, each copies 16B,
    // covering 4 rows per round (CPB*4 floats = 1KB per round).
    const int lch = (tid & 15) * 4;      // channel offset within block
    const int lr0 = tid >> 4;            // row 0..3 within each round

    auto issue_tile = [&](int ti, int bufsel) {
        float* bufp = tile + (size_t)bufsel * TK * CPB;
#pragma unroll
        for (int k = 0; k < TK / 4; ++k) {
            const int row  = lr0 + k * 4;
            const int trow = min(ti * TK + row, Tm1);   // clamp: always valid
            cp_async16(bufp + row * CPB + lch,
                       X + (size_t)trow * B_ + col0 + lch);
        }
    };

    const int nfull = NS / TK;
    const int rem   = NS - nfull * TK;

    issue_tile(0, 0); CP_COMMIT();
    issue_tile(1, 1); CP_COMMIT();
    issue_tile(2, 2); CP_COMMIT();

    for (int i = 0; i < nfull; ++i) {
        CP_WAIT2();              // tile i complete (i+1, i+2 may be pending)
        __syncthreads();

        const int buf = i % 3;
        const float* __restrict__ bp = tile + (size_t)buf * TK * CPB + tid;

        // 4-deep register ring over conflict-free LDS
        float xr[4];
#pragma unroll
        for (int j = 0; j < 4; ++j) xr[j] = bp[j * CPB];

#pragma unroll
        for (int k = 0; k < TK; ++k) {
            const float x = xr[k & 3];
            if (k + 4 < TK) xr[k & 3] = bp[(k + 4) * CPB];
            seir_step10(x, wbN, wg, ws, S, E, I, R);
            r += B_;
            __stcs(oS + r, S);
            __stcs(oE + r, E);
            __stcs(oI + r, I);
            __stcs(oR + r, R);
        }

        __syncthreads();         // everyone done reading buf
        issue_tile(i + 3, buf);  // refill same buffer for tile i+3 (clamped)
        CP_COMMIT();
    }

    if (rem > 0) {
        CP_WAIT2();              // tile nfull complete
        __syncthreads();
        const int buf = nfull % 3;
        const float* __restrict__ bp = tile + (size_t)buf * TK * CPB + tid;
        for (int k = 0; k < rem; ++k) {
            const float x = bp[k * CPB];
            seir_step10(x, wbN, wg, ws, S, E, I, R);
            r += B_;
            __stcs(oS + r, S);
            __stcs(oE + r, E);
            __stcs(oI + r, I);
            __stcs(oR + r, R);
        }
    }
}

// ------------------------------------------------ fallback (shape safety)
__global__ void seir_fallback(const float* __restrict__ X,
                              const float* __restrict__ w_beta,
                              const float* __restrict__ w_gamma,
                              const float* __restrict__ w_sigma,
                              const float* __restrict__ S0,
                              const float* __restrict__ I0,
                              const float* __restrict__ R0,
                              const float* __restrict__ Nvec,
                              float* __restrict__ out, int T, int B)
{
    const int b = blockIdx.x * blockDim.x + threadIdx.x;
    if (b >= B) return;
    const float invN = 1.0f / Nvec[b];
    const float wbN = w_beta[b] * invN;
    const float wg = w_gamma[b], ws = w_sigma[b];
    float S = S0[b], E = 0.0f, I = I0[b], R = R0[b];
    const size_t TB = (size_t)T * B;
    out[b] = S; out[TB + b] = E; out[2 * TB + b] = I; out[3 * TB + b] = R;
    for (int t = 0; t < T - 1; ++t) {
        const float x = X[(size_t)t * B + b];
        seir_step10(x, wbN, wg, ws, S, E, I, R);
        const size_t r = (size_t)(t + 1) * B + b;
        out[r] = S; out[TB + r] = E; out[2 * TB + r] = I; out[3 * TB + r] = R;
    }
}

extern "C" void kernel_launch(void* const* d_in, const int* in_sizes, int n_in,
                              void* d_out, int out_size)
{
    const float* X      = (const float*)d_in[0];
    const float* w_beta = (const float*)d_in[1];
    const float* w_gamma= (const float*)d_in[2];
    const float* w_sigma= (const float*)d_in[3];
    const float* S0     = (const float*)d_in[4];
    const float* I0     = (const float*)d_in[5];
    const float* R0     = (const float*)d_in[6];
    const float* Nvec   = (const float*)d_in[7];
    float* out = (float*)d_out;

    const int B = in_sizes[1];         // w_beta is [B]
    const int T = in_sizes[0] / B;     // X is [T, B]

    if (B == 8192 && T >= 2) {
        const int smem = NBUF * TK * CPB * (int)sizeof(float);   // 48 KB
        cudaFuncSetAttribute(seir_fused<8192>,
                             cudaFuncAttributeMaxDynamicSharedMemorySize, smem);
        seir_fused<8192><<<8192 / CPB, CPB, smem>>>(X, w_beta, w_gamma,
                                                    w_sigma, S0, I0, R0,
                                                    Nvec, out, T);
    } else {
        seir_fallback<<<(B + 127) / 128, 128>>>(X, w_beta, w_gamma, w_sigma,
                                                S0, I0, R0, Nvec, out, T, B);
    }
}